// round 12
// baseline (speedup 1.0000x reference)
#include <cuda_runtime.h>
#include <cuda_fp16.h>
#include <math.h>

// Persistent-kernel LSTM decoder. B=64, H=1024, L=2, T=128.
// 128 CTAs (1/SM), 256 threads (8 warps). R9-R11 core: warp=(ks,m2) 32x32
// tile over k16s {ks,ks+4}; continuous cp.async rings; release-atomic
// grid barrier.
// R12: (a) barrier poll-ahead at part-A kc==6 -> if satisfied, stage part-B's
// first x/W chunk inside part A's last iteration (hides the post-barrier cold
// fill); (b) fully distributed epilogue: each warp owns one 8-row output
// block, all 8 warps do the k-split reduce + cell update + stores.

#define BATCH   64
#define HID     1024
#define TSTEPS  128
#define NCTA    128
#define THREADS 256
#define SA      136    // streamed act row stride (halfs)
#define SW      136    // streamed weight row stride (halfs)
#define SR      1032   // resident weight row stride (halfs)
#define KC      128    // K chunk
#define NKC     8      // chunks per matrix
#define NX3(s)  (((s) + 1 == 3) ? 0 : (s) + 1)

// ---------------- device globals (pre-permuted fp16 weights + state) -------
__device__ __half g_Wst[2 * NCTA * 40 * HID];     // [l][cta][40 rows][k]: 32 gate + 8 FC
__device__ __half g_Whh_p[2 * NCTA * 32 * HID];   // resident recurrent weights
__device__ __half g_hbuf[4 * BATCH * HID];        // [l*2+parity][b][h]
__device__ __half g_x0[BATCH * HID];
__device__ unsigned g_bar;

// ---------------- small asm helpers ---------------------------------------
__device__ __forceinline__ unsigned sptr(const void* p) {
    return (unsigned)__cvta_generic_to_shared(p);
}
__device__ __forceinline__ void cp16(void* s, const void* g) {      // weights (.ca)
    asm volatile("cp.async.ca.shared.global [%0], [%1], 16;" :: "r"(sptr(s)), "l"(g));
}
__device__ __forceinline__ void cp16cg(void* s, const void* g) {    // acts (.cg)
    asm volatile("cp.async.cg.shared.global [%0], [%1], 16;" :: "r"(sptr(s)), "l"(g));
}
__device__ __forceinline__ void cp_commit() {
    asm volatile("cp.async.commit_group;");
}
template<int N> __device__ __forceinline__ void cp_wait() {
    asm volatile("cp.async.wait_group %0;" :: "n"(N));
}
__device__ __forceinline__ void ldsm_x4(unsigned &r0, unsigned &r1, unsigned &r2, unsigned &r3, unsigned a) {
    asm volatile("ldmatrix.sync.aligned.m8n8.x4.shared.b16 {%0,%1,%2,%3}, [%4];"
                 : "=r"(r0), "=r"(r1), "=r"(r2), "=r"(r3) : "r"(a));
}
__device__ __forceinline__ void ldsm_x2(unsigned &r0, unsigned &r1, unsigned a) {
    asm volatile("ldmatrix.sync.aligned.m8n8.x2.shared.b16 {%0,%1}, [%2];"
                 : "=r"(r0), "=r"(r1) : "r"(a));
}
__device__ __forceinline__ void hmma(float d[4], unsigned a0, unsigned a1, unsigned a2, unsigned a3,
                                     unsigned b0, unsigned b1) {
    asm volatile("mma.sync.aligned.m16n8k16.row.col.f32.f16.f16.f32 "
                 "{%0,%1,%2,%3},{%4,%5,%6,%7},{%8,%9},{%0,%1,%2,%3};"
                 : "+f"(d[0]), "+f"(d[1]), "+f"(d[2]), "+f"(d[3])
                 : "r"(a0), "r"(a1), "r"(a2), "r"(a3), "r"(b0), "r"(b1));
}
__device__ __forceinline__ float sig_(float x) { return 1.0f / (1.0f + __expf(-x)); }

// ---------------- single merged prep kernel ---------------------------------
// permuted col index pn -> (gate, unit):
//   nn=pn&15; half=nn>>3; a=(nn&7)>>1; s=nn&1; gate=half*2+s; unit=(pn>>4)*4+a
__global__ void prep_all(const float* __restrict__ Wih, const float* __restrict__ Whh,
                         const float* __restrict__ h0,  const float* __restrict__ Wfc) {
    int i = blockIdx.x * blockDim.x + threadIdx.x;
    int stride = gridDim.x * blockDim.x;
    const int totalG = 2 * NCTA * 32 * HID;
    for (int e = i; e < totalG; e += stride) {
        int k = e & (HID - 1);
        int pn = (e >> 10) & 31;
        int cta = (e >> 15) & (NCTA - 1);
        int l = e >> 22;
        int nn = pn & 15, half = nn >> 3, a = (nn & 7) >> 1, s = nn & 1;
        int gate = half * 2 + s, unit = (pn >> 4) * 4 + a;
        size_t src = (size_t)l * 4 * HID * HID + (size_t)(gate * HID + cta * 8 + unit) * HID + k;
        g_Whh_p[e] = __float2half_rn(Whh[src]);
        g_Wst[(size_t)((l * NCTA + cta) * 40 + pn) * HID + k] = __float2half_rn(Wih[src]);
    }
    const int totalF = 2 * NCTA * 8 * HID;
    for (int e = i; e < totalF; e += stride) {
        int k = e & (HID - 1);
        int u = (e >> 10) & 7;
        int cta = (e >> 13) & (NCTA - 1);
        int l = e >> 20;
        g_Wst[(size_t)((l * NCTA + cta) * 40 + 32 + u) * HID + k] =
            __float2half_rn(Wfc[(size_t)(cta * 8 + u) * HID + k]);
    }
    for (int e = i; e < BATCH * HID; e += stride) g_x0[e] = __float2half_rn(h0[e]);
    for (int e = i; e < 4 * BATCH * HID; e += stride) g_hbuf[e] = __float2half_rn(0.0f);
    if (i == 0) g_bar = 0;
}

// ---------------- split grid barrier ---------------------------------------
__device__ __forceinline__ void gbar_arrive() {
    __syncthreads();
    if (threadIdx.x == 0)
        asm volatile("red.release.gpu.add.u32 [%0], %1;" :: "l"(&g_bar), "r"(1u) : "memory");
}
__device__ __forceinline__ void gbar_wait(unsigned target) {
    if (threadIdx.x == 0) {
        unsigned v;
        do {
            asm volatile("ld.acquire.gpu.u32 %0, [%1];" : "=r"(v) : "l"(&g_bar));
        } while (v < target);
    }
    __syncthreads();
}

// ---------------- staging ---------------------------------------------------
__device__ __forceinline__ void stage_act(__half* dst, const __half* src, int k0, int tid) {
    #pragma unroll
    for (int i = 0; i < 4; i++) {
        int e = tid + i * THREADS;          // 1024 ops: 64 rows x 16 segs
        int r = e >> 4, sg = e & 15;
        cp16cg(dst + r * SA + sg * 8, src + r * HID + k0 + sg * 8);
    }
}
__device__ __forceinline__ void stage_w40(__half* dst, const __half* src, int k0, int tid) {
    #pragma unroll
    for (int i = 0; i < 3; i++) {
        int e = tid + i * THREADS;          // 640 ops: 40 rows x 16 segs
        if (e < 640) {
            int r = e >> 4, sg = e & 15;
            cp16(dst + r * SW + sg * 8, src + r * HID + k0 + sg * 8);
        }
    }
}

// ---------------- main persistent kernel ------------------------------------
__global__ __launch_bounds__(THREADS, 1) void lstm_persist(
    const float* __restrict__ bih, const float* __restrict__ bhh,
    const float* __restrict__ bfc, float* __restrict__ out)
{
    extern __shared__ __align__(16) unsigned char smem_raw[];
    __half* whhS  = (__half*)smem_raw;            // [2][32][SR]
    __half* xbufS = whhS + 2 * 32 * SR;           // [3][64][SA] continuous act ring
    __half* wbufS = xbufS + 3 * 64 * SA;          // [3][40][SW] streamed-W ring (+ epi scratch)
    float*  cS    = (float*)(wbufS + 3 * 40 * SW);// [2][64][8]
    float*  biasS = cS + 2 * 64 * 8;              // [2][32]
    float*  fcbS  = biasS + 64;                   // [8]
    int*    flagS = (int*)(fcbS + 8);             // [1] barrier poll-ahead flag
    float*  wscr  = (float*)wbufS;                // epilogue reduce scratch

    const int tid  = threadIdx.x;
    const int warp = tid >> 5;
    const int lane = tid & 31;
    const int m2   = warp & 1;     // 32-row M half
    const int ks   = warp >> 1;    // k16 split (k16 in {ks, ks+4})
    const int cta  = blockIdx.x;
    const int j0   = cta * 8;

    const unsigned ABUF = 64 * SA * 2;   // act buffer stride (bytes)
    const unsigned WBUF = 40 * SW * 2;   // W buffer stride (bytes)
    const int ABUFH = 64 * SA;           // act buffer stride (halfs)
    const int WBUFH = 40 * SW;

    // ---- load resident Whh (both layers) ----
    for (int l = 0; l < 2; l++) {
        const __half* src = g_Whh_p + (size_t)(l * NCTA + cta) * 32 * HID;
        for (int i = 0; i < 16; i++) {
            int e = tid + i * THREADS;      // 32 rows x 128 segs
            int r = e >> 7, sg = e & 127;
            cp16(whhS + l * 32 * SR + r * SR + sg * 8, src + r * HID + sg * 8);
        }
    }
    cp_commit();
    // ---- biases / cell state ----
    if (tid < 64) {
        int l = tid >> 5, pn = tid & 31;
        int nn = pn & 15, half = nn >> 3, a = (nn & 7) >> 1, s = nn & 1;
        int gate = half * 2 + s, unit = (pn >> 4) * 4 + a;
        int row = gate * HID + j0 + unit;
        biasS[l * 32 + pn] = bih[l * 4 * HID + row] + bhh[l * 4 * HID + row];
    }
    if (tid < 8) fcbS[tid] = bfc[j0 + tid];
    if (tid == 0) flagS[0] = 0;
    #pragma unroll
    for (int i = 0; i < 4; i++) cS[tid + i * THREADS] = 0.0f;
    cp_wait<0>();
    __syncthreads();

    // per-lane fragment base addresses (slot-0; slot delta added at use)
    const unsigned xbA0[2] = {
        sptr(xbufS) + ((m2 * 32 + 0  + (lane & 15)) * SA + (lane >> 4) * 8) * 2,
        sptr(xbufS) + ((m2 * 32 + 16 + (lane & 15)) * SA + (lane >> 4) * 8) * 2 };
    const unsigned wbB0[2] = {
        sptr(wbufS) + ((0  + (lane & 15)) * SW + (lane >> 4) * 8) * 2,
        sptr(wbufS) + ((16 + (lane & 15)) * SW + (lane >> 4) * 8) * 2 };
    const unsigned fcB0 =
        sptr(wbufS) + ((32 + (lane & 7)) * SW + ((lane >> 3) & 1) * 8) * 2;
    const unsigned whB[2][2] = {
        { sptr(whhS) + ((0  + (lane & 15)) * SR + (lane >> 4) * 8) * 2,
          sptr(whhS) + ((16 + (lane & 15)) * SR + (lane >> 4) * 8) * 2 },
        { sptr(whhS) + ((32 + 0  + (lane & 15)) * SR + (lane >> 4) * 8) * 2,
          sptr(whhS) + ((32 + 16 + (lane & 15)) * SR + (lane >> 4) * 8) * 2 } };

    unsigned barTarget = 0;
    const int r = lane >> 2, a4 = lane & 3;

    // ring slot state (continuous across phases)
    int s_stage = 0, s_cons = 0;   // act ring
    int w_stage = 0, w_cons = 0;   // W ring

    // ---- prologue: stage part-A chunks 0,1 of the first phase ----
    {
        const __half* h00 = g_hbuf + (0 + 1) * BATCH * HID;   // t=0: q=1
        stage_act(xbufS + s_stage * ABUFH, h00, 0, tid); cp_commit(); s_stage = NX3(s_stage);
        stage_act(xbufS + s_stage * ABUFH, h00, KC, tid); cp_commit(); s_stage = NX3(s_stage);
    }

    for (int t = 0; t < TSTEPS; t++) {
        const int p = t & 1, q = p ^ 1;
        #pragma unroll 1
        for (int l = 0; l < 2; l++) {
            const __half* xsrc = (l == 0)
                ? ((t == 0) ? g_x0 : g_hbuf + (2 + q) * BATCH * HID)
                : g_hbuf + (0 + p) * BATCH * HID;
            const __half* hsrc = g_hbuf + (l * 2 + q) * BATCH * HID;
            __half* hdst = g_hbuf + (l * 2 + p) * BATCH * HID;
            const __half* wsrc = g_Wst + (size_t)(l * NCTA + cta) * 40 * HID;
            // next phase's part-A input (legal already: written >= 1 phase ago)
            const __half* nhsrc = (l == 0) ? g_hbuf + (2 + q) * BATCH * HID
                                           : g_hbuf + (0 + p) * BATCH * HID;
            const bool fc_phase = (l == 0) && (t > 0);
            const bool last_phase = (l == 1) && (t == TSTEPS - 1);

            float acc[2][4][4];
            #pragma unroll
            for (int a = 0; a < 2; a++)
                #pragma unroll
                for (int b = 0; b < 4; b++)
                    #pragma unroll
                    for (int c2 = 0; c2 < 4; c2++) acc[a][b][c2] = 0.0f;
            float fca[2][4] = {{0,0,0,0},{0,0,0,0}};

            // ===== part A: h_rec @ Whh (resident; chunks 0,1 already staged)
            #pragma unroll 1
            for (int kc = 0; kc < NKC; kc++) {
                cp_wait<1>();
                __syncthreads();
                if (kc + 2 < NKC) {
                    stage_act(xbufS + s_stage * ABUFH, hsrc, (kc + 2) * KC, tid);
                    s_stage = NX3(s_stage);
                } else if (kc == NKC - 2) {
                    // barrier poll-ahead (non-blocking): one acquire read
                    if (tid == 0) {
                        unsigned v;
                        asm volatile("ld.acquire.gpu.u32 %0, [%1];" : "=r"(v) : "l"(&g_bar));
                        flagS[0] = (v >= barTarget) ? 1 : 0;
                    }
                } else if (flagS[0]) {
                    // kc == NKC-1, barrier already satisfied (flag ordered by
                    // this iteration's __syncthreads): stage part-B chunk 0 now
                    stage_act(xbufS + s_stage * ABUFH, xsrc, 0, tid);
                    stage_w40(wbufS + w_stage * WBUFH, wsrc, 0, tid);
                    s_stage = NX3(s_stage); w_stage = NX3(w_stage);
                }
                cp_commit();
                const unsigned xd = (unsigned)s_cons * ABUF;
                s_cons = NX3(s_cons);
                #pragma unroll
                for (int j = 0; j < 2; j++) {
                    const int k16 = ks + j * 4;
                    unsigned a0[2][4], b0[2][4];
                    #pragma unroll
                    for (int mf = 0; mf < 2; mf++)
                        ldsm_x4(a0[mf][0], a0[mf][1], a0[mf][2], a0[mf][3],
                                xbA0[mf] + xd + k16 * 32);
                    #pragma unroll
                    for (int cg = 0; cg < 2; cg++)
                        ldsm_x4(b0[cg][0], b0[cg][1], b0[cg][2], b0[cg][3],
                                whB[l][cg] + (kc * KC + k16 * 16) * 2);
                    #pragma unroll
                    for (int mf = 0; mf < 2; mf++)
                        #pragma unroll
                        for (int cg = 0; cg < 2; cg++) {
                            hmma(acc[mf][cg * 2 + 0], a0[mf][0], a0[mf][1], a0[mf][2], a0[mf][3],
                                 b0[cg][0], b0[cg][2]);
                            hmma(acc[mf][cg * 2 + 1], a0[mf][0], a0[mf][1], a0[mf][2], a0[mf][3],
                                 b0[cg][1], b0[cg][3]);
                        }
                }
            }

            // ===== barrier + part-B head staging (early path skips both) =====
            {
                const int early = flagS[0];   // unchanged since last sync
                if (!early) {
                    gbar_wait(barTarget);
                    stage_act(xbufS + s_stage * ABUFH, xsrc, 0, tid);
                    stage_w40(wbufS + w_stage * WBUFH, wsrc, 0, tid);
                    cp_commit();
                    s_stage = NX3(s_stage); w_stage = NX3(w_stage);
                }
                stage_act(xbufS + s_stage * ABUFH, xsrc, KC, tid);
                stage_w40(wbufS + w_stage * WBUFH, wsrc, KC, tid);
                cp_commit();
                s_stage = NX3(s_stage); w_stage = NX3(w_stage);
            }

            // ===== part B: x @ [Wih | Wfc] streamed =====
            #pragma unroll 1
            for (int kc = 0; kc < NKC; kc++) {
                cp_wait<1>();
                __syncthreads();
                if (kc + 2 < NKC) {
                    stage_act(xbufS + s_stage * ABUFH, xsrc, (kc + 2) * KC, tid);
                    stage_w40(wbufS + w_stage * WBUFH, wsrc, (kc + 2) * KC, tid);
                    s_stage = NX3(s_stage); w_stage = NX3(w_stage);
                } else if (kc == NKC - 2 && !last_phase) {
                    // prefetch next phase's part-A chunk 0
                    stage_act(xbufS + s_stage * ABUFH, nhsrc, 0, tid);
                    s_stage = NX3(s_stage);
                }
                cp_commit();
                const unsigned xd = (unsigned)s_cons * ABUF;
                const unsigned wd = (unsigned)w_cons * WBUF;
                s_cons = NX3(s_cons); w_cons = NX3(w_cons);
                #pragma unroll
                for (int j = 0; j < 2; j++) {
                    const int k16 = ks + j * 4;
                    unsigned a0[2][4], b0[2][4];
                    #pragma unroll
                    for (int mf = 0; mf < 2; mf++)
                        ldsm_x4(a0[mf][0], a0[mf][1], a0[mf][2], a0[mf][3],
                                xbA0[mf] + xd + k16 * 32);
                    #pragma unroll
                    for (int cg = 0; cg < 2; cg++)
                        ldsm_x4(b0[cg][0], b0[cg][1], b0[cg][2], b0[cg][3],
                                wbB0[cg] + wd + k16 * 32);
                    #pragma unroll
                    for (int mf = 0; mf < 2; mf++)
                        #pragma unroll
                        for (int cg = 0; cg < 2; cg++) {
                            hmma(acc[mf][cg * 2 + 0], a0[mf][0], a0[mf][1], a0[mf][2], a0[mf][3],
                                 b0[cg][0], b0[cg][2]);
                            hmma(acc[mf][cg * 2 + 1], a0[mf][0], a0[mf][1], a0[mf][2], a0[mf][3],
                                 b0[cg][1], b0[cg][3]);
                        }
                    if (fc_phase) {
                        unsigned f0, f1;
                        ldsm_x2(f0, f1, fcB0 + wd + k16 * 32);
                        #pragma unroll
                        for (int mf = 0; mf < 2; mf++)
                            hmma(fca[mf], a0[mf][0], a0[mf][1], a0[mf][2], a0[mf][3], f0, f1);
                    }
                }
            }

            // ===== distributed epilogue: each warp owns block (mf,rp)=(ks>>1,ks&1)
            __syncthreads();           // all W-ring reads done before scratch reuse
            #pragma unroll
            for (int bi = 0; bi < 4; bi++) {
                if (bi == ks) continue;
                const int wi = (ks < bi) ? ks : ks - 1;
                float* sp = wscr + (((bi * 2 + m2) * 3 + wi) * 32 + lane) * 10;
                const int mf = bi >> 1, k = (bi & 1) * 2;
                #pragma unroll
                for (int nf = 0; nf < 4; nf++)
                    #pragma unroll
                    for (int cc = 0; cc < 2; cc++)
                        sp[nf * 2 + cc] = acc[mf][nf][k + cc];
                sp[8] = fca[mf][k + 0];
                sp[9] = fca[mf][k + 1];
            }
            __syncthreads();
            {
                const int mf = ks >> 1, rp = ks & 1, k = rp * 2;
                float g8[8], f2[2];
                #pragma unroll
                for (int nf = 0; nf < 4; nf++)
                    #pragma unroll
                    for (int cc = 0; cc < 2; cc++)
                        g8[nf * 2 + cc] = acc[mf][nf][k + cc];
                f2[0] = fca[mf][k + 0]; f2[1] = fca[mf][k + 1];
                #pragma unroll
                for (int wi = 0; wi < 3; wi++) {
                    const float* sp = wscr + (((ks * 2 + m2) * 3 + wi) * 32 + lane) * 10;
                    #pragma unroll
                    for (int e = 0; e < 8; e++) g8[e] += sp[e];
                    f2[0] += sp[8]; f2[1] += sp[9];
                }
                const int b = m2 * 32 + mf * 16 + rp * 8 + r;
                float* crow = cS + l * 64 * 8;
                #pragma unroll
                for (int ug = 0; ug < 2; ug++) {
                    const int u = ug * 4 + a4;
                    float iv = g8[(ug * 2 + 0) * 2 + 0] + biasS[l * 32 + ug * 16 + a4 * 2 + 0];
                    float fv = g8[(ug * 2 + 0) * 2 + 1] + biasS[l * 32 + ug * 16 + a4 * 2 + 1];
                    float gv = g8[(ug * 2 + 1) * 2 + 0] + biasS[l * 32 + ug * 16 + 8 + a4 * 2 + 0];
                    float ov = g8[(ug * 2 + 1) * 2 + 1] + biasS[l * 32 + ug * 16 + 8 + a4 * 2 + 1];
                    float cn = sig_(fv) * crow[b * 8 + u] + sig_(iv) * tanhf(gv);
                    crow[b * 8 + u] = cn;
                    hdst[b * HID + j0 + u] = __float2half_rn(sig_(ov) * tanhf(cn));
                }
                if (fc_phase) {
                    float* op = out + (size_t)(t - 1) * BATCH * HID;
                    op[b * HID + j0 + a4 * 2 + 0] = f2[0] + fcbS[a4 * 2 + 0];
                    op[b * HID + j0 + a4 * 2 + 1] = f2[1] + fcbS[a4 * 2 + 1];
                }
            }
            gbar_arrive();
            barTarget += NCTA;
            if (!last_phase) {
                // stage next phase's part-A chunk 1 (chunk 0 staged at B kc=6)
                stage_act(xbufS + s_stage * ABUFH, nhsrc, KC, tid);
                cp_commit();
                s_stage = NX3(s_stage);
            }
        }
    }

    // ===== final FC for t = T-1 (x = h1 written at t=127, parity 1) =====
    {
        gbar_wait(barTarget);
        const __half* xsrc = g_hbuf + (2 + 1) * BATCH * HID;
        const __half* wsrc = g_Wst + (size_t)(0 * NCTA + cta) * 40 * HID;
        float fca[2][4] = {{0,0,0,0},{0,0,0,0}};
        #pragma unroll
        for (int i = 0; i < 2; i++) {
            stage_act(xbufS + s_stage * ABUFH, xsrc, i * KC, tid);
            stage_w40(wbufS + w_stage * WBUFH, wsrc, i * KC, tid);
            cp_commit();
            s_stage = NX3(s_stage); w_stage = NX3(w_stage);
        }
        #pragma unroll 1
        for (int kc = 0; kc < NKC; kc++) {
            cp_wait<1>();
            __syncthreads();
            if (kc + 2 < NKC) {
                stage_act(xbufS + s_stage * ABUFH, xsrc, (kc + 2) * KC, tid);
                stage_w40(wbufS + w_stage * WBUFH, wsrc, (kc + 2) * KC, tid);
                s_stage = NX3(s_stage); w_stage = NX3(w_stage);
            }
            cp_commit();
            const unsigned xd = (unsigned)s_cons * ABUF;
            const unsigned wd = (unsigned)w_cons * WBUF;
            s_cons = NX3(s_cons); w_cons = NX3(w_cons);
            #pragma unroll
            for (int j = 0; j < 2; j++) {
                const int k16 = ks + j * 4;
                unsigned f0, f1;
                ldsm_x2(f0, f1, fcB0 + wd + k16 * 32);
                #pragma unroll
                for (int mf = 0; mf < 2; mf++) {
                    unsigned a0, a1, a2, a3;
                    ldsm_x4(a0, a1, a2, a3, xbA0[mf] + xd + k16 * 32);
                    hmma(fca[mf], a0, a1, a2, a3, f0, f1);
                }
            }
        }
        // distributed FC epilogue (same block-ownership scheme)
        __syncthreads();
        #pragma unroll
        for (int bi = 0; bi < 4; bi++) {
            if (bi == ks) continue;
            const int wi = (ks < bi) ? ks : ks - 1;
            float* sp = wscr + (((bi * 2 + m2) * 3 + wi) * 32 + lane) * 10;
            const int mf = bi >> 1, k = (bi & 1) * 2;
            sp[8] = fca[mf][k + 0];
            sp[9] = fca[mf][k + 1];
        }
        __syncthreads();
        {
            const int mf = ks >> 1, rp = ks & 1, k = rp * 2;
            float f2[2] = { fca[mf][k + 0], fca[mf][k + 1] };
            #pragma unroll
            for (int wi = 0; wi < 3; wi++) {
                const float* sp = wscr + (((ks * 2 + m2) * 3 + wi) * 32 + lane) * 10;
                f2[0] += sp[8]; f2[1] += sp[9];
            }
            const int b = m2 * 32 + mf * 16 + rp * 8 + r;
            float* op = out + (size_t)(TSTEPS - 1) * BATCH * HID;
            op[b * HID + j0 + a4 * 2 + 0] = f2[0] + fcbS[a4 * 2 + 0];
            op[b * HID + j0 + a4 * 2 + 1] = f2[1] + fcbS[a4 * 2 + 1];
        }
    }
}

// ---------------- host launch -----------------------------------------------
extern "C" void kernel_launch(void* const* d_in, const int* in_sizes, int n_in,
                              void* d_out, int out_size) {
    const float* h0  = (const float*)d_in[0];
    const float* Wih = (const float*)d_in[1];
    const float* Whh = (const float*)d_in[2];
    const float* bih = (const float*)d_in[3];
    const float* bhh = (const float*)d_in[4];
    const float* Wfc = (const float*)d_in[5];
    const float* bfc = (const float*)d_in[6];
    float* out = (float*)d_out;

    const int smem = (2 * 32 * SR + 3 * 64 * SA + 3 * 40 * SW) * 2
                   + (2 * 64 * 8 + 64 + 8 + 4) * 4;
    cudaFuncSetAttribute(lstm_persist, cudaFuncAttributeMaxDynamicSharedMemorySize, smem);

    prep_all<<<2048, 256>>>(Wih, Whh, h0, Wfc);
    lstm_persist<<<NCTA, THREADS, smem>>>(bih, bhh, bfc, out);
}

// round 13
// speedup vs baseline: 1.0378x; 1.0378x over previous
#include <cuda_runtime.h>
#include <cuda_fp16.h>
#include <math.h>

// Persistent-kernel LSTM decoder. B=64, H=1024, L=2, T=128.
// 128 CTAs (1/SM), 256 threads (8 warps). R9-R11 core: warp=(ks,m2) 32x32
// tile over k16s {ks,ks+4}; continuous cp.async rings; release-atomic
// grid barrier; part-A/barrier/part-B phase order.
// R13 = R11 + distributed epilogue ONLY (R12's poll-ahead dropped: it
// restructured the hot loop and regressed 53%). Epilogue: each warp owns
// output block (mf,rp)=(ks>>1,ks&1); scratch is SoA [elem][lane] ->
// conflict-free; all 8 warps share the k-split reduce + tanh/sigmoid tail.

#define BATCH   64
#define HID     1024
#define TSTEPS  128
#define NCTA    128
#define THREADS 256
#define SA      136    // streamed act row stride (halfs)
#define SW      136    // streamed weight row stride (halfs)
#define SR      1032   // resident weight row stride (halfs)
#define KC      128    // K chunk
#define NKC     8      // chunks per matrix
#define NX3(s)  (((s) + 1 == 3) ? 0 : (s) + 1)

// ---------------- device globals (pre-permuted fp16 weights + state) -------
__device__ __half g_Wst[2 * NCTA * 40 * HID];     // [l][cta][40 rows][k]: 32 gate + 8 FC
__device__ __half g_Whh_p[2 * NCTA * 32 * HID];   // resident recurrent weights
__device__ __half g_hbuf[4 * BATCH * HID];        // [l*2+parity][b][h]
__device__ __half g_x0[BATCH * HID];
__device__ unsigned g_bar;

// ---------------- small asm helpers ---------------------------------------
__device__ __forceinline__ unsigned sptr(const void* p) {
    return (unsigned)__cvta_generic_to_shared(p);
}
__device__ __forceinline__ void cp16(void* s, const void* g) {      // weights (.ca)
    asm volatile("cp.async.ca.shared.global [%0], [%1], 16;" :: "r"(sptr(s)), "l"(g));
}
__device__ __forceinline__ void cp16cg(void* s, const void* g) {    // acts (.cg)
    asm volatile("cp.async.cg.shared.global [%0], [%1], 16;" :: "r"(sptr(s)), "l"(g));
}
__device__ __forceinline__ void cp_commit() {
    asm volatile("cp.async.commit_group;");
}
template<int N> __device__ __forceinline__ void cp_wait() {
    asm volatile("cp.async.wait_group %0;" :: "n"(N));
}
__device__ __forceinline__ void ldsm_x4(unsigned &r0, unsigned &r1, unsigned &r2, unsigned &r3, unsigned a) {
    asm volatile("ldmatrix.sync.aligned.m8n8.x4.shared.b16 {%0,%1,%2,%3}, [%4];"
                 : "=r"(r0), "=r"(r1), "=r"(r2), "=r"(r3) : "r"(a));
}
__device__ __forceinline__ void ldsm_x2(unsigned &r0, unsigned &r1, unsigned a) {
    asm volatile("ldmatrix.sync.aligned.m8n8.x2.shared.b16 {%0,%1}, [%2];"
                 : "=r"(r0), "=r"(r1) : "r"(a));
}
__device__ __forceinline__ void hmma(float d[4], unsigned a0, unsigned a1, unsigned a2, unsigned a3,
                                     unsigned b0, unsigned b1) {
    asm volatile("mma.sync.aligned.m16n8k16.row.col.f32.f16.f16.f32 "
                 "{%0,%1,%2,%3},{%4,%5,%6,%7},{%8,%9},{%0,%1,%2,%3};"
                 : "+f"(d[0]), "+f"(d[1]), "+f"(d[2]), "+f"(d[3])
                 : "r"(a0), "r"(a1), "r"(a2), "r"(a3), "r"(b0), "r"(b1));
}
__device__ __forceinline__ float sig_(float x) { return 1.0f / (1.0f + __expf(-x)); }

// ---------------- single merged prep kernel ---------------------------------
// permuted col index pn -> (gate, unit):
//   nn=pn&15; half=nn>>3; a=(nn&7)>>1; s=nn&1; gate=half*2+s; unit=(pn>>4)*4+a
__global__ void prep_all(const float* __restrict__ Wih, const float* __restrict__ Whh,
                         const float* __restrict__ h0,  const float* __restrict__ Wfc) {
    int i = blockIdx.x * blockDim.x + threadIdx.x;
    int stride = gridDim.x * blockDim.x;
    const int totalG = 2 * NCTA * 32 * HID;
    for (int e = i; e < totalG; e += stride) {
        int k = e & (HID - 1);
        int pn = (e >> 10) & 31;
        int cta = (e >> 15) & (NCTA - 1);
        int l = e >> 22;
        int nn = pn & 15, half = nn >> 3, a = (nn & 7) >> 1, s = nn & 1;
        int gate = half * 2 + s, unit = (pn >> 4) * 4 + a;
        size_t src = (size_t)l * 4 * HID * HID + (size_t)(gate * HID + cta * 8 + unit) * HID + k;
        g_Whh_p[e] = __float2half_rn(Whh[src]);
        g_Wst[(size_t)((l * NCTA + cta) * 40 + pn) * HID + k] = __float2half_rn(Wih[src]);
    }
    const int totalF = 2 * NCTA * 8 * HID;
    for (int e = i; e < totalF; e += stride) {
        int k = e & (HID - 1);
        int u = (e >> 10) & 7;
        int cta = (e >> 13) & (NCTA - 1);
        int l = e >> 20;
        g_Wst[(size_t)((l * NCTA + cta) * 40 + 32 + u) * HID + k] =
            __float2half_rn(Wfc[(size_t)(cta * 8 + u) * HID + k]);
    }
    for (int e = i; e < BATCH * HID; e += stride) g_x0[e] = __float2half_rn(h0[e]);
    for (int e = i; e < 4 * BATCH * HID; e += stride) g_hbuf[e] = __float2half_rn(0.0f);
    if (i == 0) g_bar = 0;
}

// ---------------- split grid barrier ---------------------------------------
__device__ __forceinline__ void gbar_arrive() {
    __syncthreads();
    if (threadIdx.x == 0)
        asm volatile("red.release.gpu.add.u32 [%0], %1;" :: "l"(&g_bar), "r"(1u) : "memory");
}
__device__ __forceinline__ void gbar_wait(unsigned target) {
    if (threadIdx.x == 0) {
        unsigned v;
        do {
            asm volatile("ld.acquire.gpu.u32 %0, [%1];" : "=r"(v) : "l"(&g_bar));
        } while (v < target);
    }
    __syncthreads();
}

// ---------------- staging ---------------------------------------------------
__device__ __forceinline__ void stage_act(__half* dst, const __half* src, int k0, int tid) {
    #pragma unroll
    for (int i = 0; i < 4; i++) {
        int e = tid + i * THREADS;          // 1024 ops: 64 rows x 16 segs
        int r = e >> 4, sg = e & 15;
        cp16cg(dst + r * SA + sg * 8, src + r * HID + k0 + sg * 8);
    }
}
__device__ __forceinline__ void stage_w40(__half* dst, const __half* src, int k0, int tid) {
    #pragma unroll
    for (int i = 0; i < 3; i++) {
        int e = tid + i * THREADS;          // 640 ops: 40 rows x 16 segs
        if (e < 640) {
            int r = e >> 4, sg = e & 15;
            cp16(dst + r * SW + sg * 8, src + r * HID + k0 + sg * 8);
        }
    }
}

// ---------------- main persistent kernel ------------------------------------
__global__ __launch_bounds__(THREADS, 1) void lstm_persist(
    const float* __restrict__ bih, const float* __restrict__ bhh,
    const float* __restrict__ bfc, float* __restrict__ out)
{
    extern __shared__ __align__(16) unsigned char smem_raw[];
    __half* whhS  = (__half*)smem_raw;            // [2][32][SR]
    __half* xbufS = whhS + 2 * 32 * SR;           // [3][64][SA] continuous act ring
    __half* wbufS = xbufS + 3 * 64 * SA;          // [3][40][SW] streamed-W ring (+ epi scratch)
    float*  cS    = (float*)(wbufS + 3 * 40 * SW);// [2][64][8]
    float*  biasS = cS + 2 * 64 * 8;              // [2][32]
    float*  fcbS  = biasS + 64;                   // [8]
    float*  wscr  = (float*)wbufS;                // epilogue reduce scratch (SoA)

    const int tid  = threadIdx.x;
    const int warp = tid >> 5;
    const int lane = tid & 31;
    const int m2   = warp & 1;     // 32-row M half
    const int ks   = warp >> 1;    // k16 split (k16 in {ks, ks+4})
    const int cta  = blockIdx.x;
    const int j0   = cta * 8;

    const unsigned ABUF = 64 * SA * 2;   // act buffer stride (bytes)
    const unsigned WBUF = 40 * SW * 2;   // W buffer stride (bytes)
    const int ABUFH = 64 * SA;           // act buffer stride (halfs)
    const int WBUFH = 40 * SW;

    // ---- load resident Whh (both layers) ----
    for (int l = 0; l < 2; l++) {
        const __half* src = g_Whh_p + (size_t)(l * NCTA + cta) * 32 * HID;
        for (int i = 0; i < 16; i++) {
            int e = tid + i * THREADS;      // 32 rows x 128 segs
            int r = e >> 7, sg = e & 127;
            cp16(whhS + l * 32 * SR + r * SR + sg * 8, src + r * HID + sg * 8);
        }
    }
    cp_commit();
    // ---- biases / cell state ----
    if (tid < 64) {
        int l = tid >> 5, pn = tid & 31;
        int nn = pn & 15, half = nn >> 3, a = (nn & 7) >> 1, s = nn & 1;
        int gate = half * 2 + s, unit = (pn >> 4) * 4 + a;
        int row = gate * HID + j0 + unit;
        biasS[l * 32 + pn] = bih[l * 4 * HID + row] + bhh[l * 4 * HID + row];
    }
    if (tid < 8) fcbS[tid] = bfc[j0 + tid];
    #pragma unroll
    for (int i = 0; i < 4; i++) cS[tid + i * THREADS] = 0.0f;
    cp_wait<0>();
    __syncthreads();

    // per-lane fragment base addresses (slot-0; slot delta added at use)
    const unsigned xbA0[2] = {
        sptr(xbufS) + ((m2 * 32 + 0  + (lane & 15)) * SA + (lane >> 4) * 8) * 2,
        sptr(xbufS) + ((m2 * 32 + 16 + (lane & 15)) * SA + (lane >> 4) * 8) * 2 };
    const unsigned wbB0[2] = {
        sptr(wbufS) + ((0  + (lane & 15)) * SW + (lane >> 4) * 8) * 2,
        sptr(wbufS) + ((16 + (lane & 15)) * SW + (lane >> 4) * 8) * 2 };
    const unsigned fcB0 =
        sptr(wbufS) + ((32 + (lane & 7)) * SW + ((lane >> 3) & 1) * 8) * 2;
    const unsigned whB[2][2] = {
        { sptr(whhS) + ((0  + (lane & 15)) * SR + (lane >> 4) * 8) * 2,
          sptr(whhS) + ((16 + (lane & 15)) * SR + (lane >> 4) * 8) * 2 },
        { sptr(whhS) + ((32 + 0  + (lane & 15)) * SR + (lane >> 4) * 8) * 2,
          sptr(whhS) + ((32 + 16 + (lane & 15)) * SR + (lane >> 4) * 8) * 2 } };

    unsigned barTarget = 0;
    const int r = lane >> 2, a4 = lane & 3;

    // ring slot state (continuous across phases)
    int s_stage = 0, s_cons = 0;   // act ring
    int w_stage = 0, w_cons = 0;   // W ring

    // ---- prologue: stage part-A chunks 0,1 of the first phase ----
    {
        const __half* h00 = g_hbuf + (0 + 1) * BATCH * HID;   // t=0: q=1
        stage_act(xbufS + s_stage * ABUFH, h00, 0, tid); cp_commit(); s_stage = NX3(s_stage);
        stage_act(xbufS + s_stage * ABUFH, h00, KC, tid); cp_commit(); s_stage = NX3(s_stage);
    }

    for (int t = 0; t < TSTEPS; t++) {
        const int p = t & 1, q = p ^ 1;
        #pragma unroll 1
        for (int l = 0; l < 2; l++) {
            const __half* xsrc = (l == 0)
                ? ((t == 0) ? g_x0 : g_hbuf + (2 + q) * BATCH * HID)
                : g_hbuf + (0 + p) * BATCH * HID;
            const __half* hsrc = g_hbuf + (l * 2 + q) * BATCH * HID;
            __half* hdst = g_hbuf + (l * 2 + p) * BATCH * HID;
            const __half* wsrc = g_Wst + (size_t)(l * NCTA + cta) * 40 * HID;
            // next phase's part-A input (legal already: written >= 1 phase ago)
            const __half* nhsrc = (l == 0) ? g_hbuf + (2 + q) * BATCH * HID
                                           : g_hbuf + (0 + p) * BATCH * HID;
            const bool fc_phase = (l == 0) && (t > 0);
            const bool last_phase = (l == 1) && (t == TSTEPS - 1);

            float acc[2][4][4];
            #pragma unroll
            for (int a = 0; a < 2; a++)
                #pragma unroll
                for (int b = 0; b < 4; b++)
                    #pragma unroll
                    for (int c2 = 0; c2 < 4; c2++) acc[a][b][c2] = 0.0f;
            float fca[2][4] = {{0,0,0,0},{0,0,0,0}};

            // ===== part A: h_rec @ Whh (resident; chunks 0,1 already staged)
            #pragma unroll 1
            for (int kc = 0; kc < NKC; kc++) {
                cp_wait<1>();
                __syncthreads();
                if (kc + 2 < NKC) {
                    stage_act(xbufS + s_stage * ABUFH, hsrc, (kc + 2) * KC, tid);
                    s_stage = NX3(s_stage);
                }
                cp_commit();
                const unsigned xd = (unsigned)s_cons * ABUF;
                s_cons = NX3(s_cons);
                #pragma unroll
                for (int j = 0; j < 2; j++) {
                    const int k16 = ks + j * 4;
                    unsigned a0[2][4], b0[2][4];
                    #pragma unroll
                    for (int mf = 0; mf < 2; mf++)
                        ldsm_x4(a0[mf][0], a0[mf][1], a0[mf][2], a0[mf][3],
                                xbA0[mf] + xd + k16 * 32);
                    #pragma unroll
                    for (int cg = 0; cg < 2; cg++)
                        ldsm_x4(b0[cg][0], b0[cg][1], b0[cg][2], b0[cg][3],
                                whB[l][cg] + (kc * KC + k16 * 16) * 2);
                    #pragma unroll
                    for (int mf = 0; mf < 2; mf++)
                        #pragma unroll
                        for (int cg = 0; cg < 2; cg++) {
                            hmma(acc[mf][cg * 2 + 0], a0[mf][0], a0[mf][1], a0[mf][2], a0[mf][3],
                                 b0[cg][0], b0[cg][2]);
                            hmma(acc[mf][cg * 2 + 1], a0[mf][0], a0[mf][1], a0[mf][2], a0[mf][3],
                                 b0[cg][1], b0[cg][3]);
                        }
                }
            }

            // ===== barrier wait (mostly satisfied already) =====
            gbar_wait(barTarget);

            // ===== part B: x @ [Wih | Wfc] streamed =====
            #pragma unroll
            for (int i = 0; i < 2; i++) {
                stage_act(xbufS + s_stage * ABUFH, xsrc, i * KC, tid);
                stage_w40(wbufS + w_stage * WBUFH, wsrc, i * KC, tid);
                cp_commit();
                s_stage = NX3(s_stage); w_stage = NX3(w_stage);
            }
            #pragma unroll 1
            for (int kc = 0; kc < NKC; kc++) {
                cp_wait<1>();
                __syncthreads();
                if (kc + 2 < NKC) {
                    stage_act(xbufS + s_stage * ABUFH, xsrc, (kc + 2) * KC, tid);
                    stage_w40(wbufS + w_stage * WBUFH, wsrc, (kc + 2) * KC, tid);
                    s_stage = NX3(s_stage); w_stage = NX3(w_stage);
                } else if (kc == NKC - 2 && !last_phase) {
                    // prefetch next phase's part-A chunk 0
                    stage_act(xbufS + s_stage * ABUFH, nhsrc, 0, tid);
                    s_stage = NX3(s_stage);
                }
                cp_commit();
                const unsigned xd = (unsigned)s_cons * ABUF;
                const unsigned wd = (unsigned)w_cons * WBUF;
                s_cons = NX3(s_cons); w_cons = NX3(w_cons);
                #pragma unroll
                for (int j = 0; j < 2; j++) {
                    const int k16 = ks + j * 4;
                    unsigned a0[2][4], b0[2][4];
                    #pragma unroll
                    for (int mf = 0; mf < 2; mf++)
                        ldsm_x4(a0[mf][0], a0[mf][1], a0[mf][2], a0[mf][3],
                                xbA0[mf] + xd + k16 * 32);
                    #pragma unroll
                    for (int cg = 0; cg < 2; cg++)
                        ldsm_x4(b0[cg][0], b0[cg][1], b0[cg][2], b0[cg][3],
                                wbB0[cg] + wd + k16 * 32);
                    #pragma unroll
                    for (int mf = 0; mf < 2; mf++)
                        #pragma unroll
                        for (int cg = 0; cg < 2; cg++) {
                            hmma(acc[mf][cg * 2 + 0], a0[mf][0], a0[mf][1], a0[mf][2], a0[mf][3],
                                 b0[cg][0], b0[cg][2]);
                            hmma(acc[mf][cg * 2 + 1], a0[mf][0], a0[mf][1], a0[mf][2], a0[mf][3],
                                 b0[cg][1], b0[cg][3]);
                        }
                    if (fc_phase) {
                        unsigned f0, f1;
                        ldsm_x2(f0, f1, fcB0 + wd + k16 * 32);
                        #pragma unroll
                        for (int mf = 0; mf < 2; mf++)
                            hmma(fca[mf], a0[mf][0], a0[mf][1], a0[mf][2], a0[mf][3], f0, f1);
                    }
                }
            }

            // ===== distributed epilogue (SoA scratch, conflict-free) ========
            // each warp owns output block (mf,rp) = (ks>>1, ks&1)
            __syncthreads();           // all W-ring reads done before scratch reuse
            #pragma unroll
            for (int bi = 0; bi < 4; bi++) {
                if (bi == ks) continue;
                const int wi = (ks < bi) ? ks : ks - 1;
                float* sp = wscr + (((bi * 2 + m2) * 3 + wi) * 10) * 32 + lane;
                const int mf = bi >> 1, k = (bi & 1) * 2;
                #pragma unroll
                for (int nf = 0; nf < 4; nf++)
                    #pragma unroll
                    for (int cc = 0; cc < 2; cc++)
                        sp[(nf * 2 + cc) * 32] = acc[mf][nf][k + cc];
                sp[8 * 32] = fca[mf][k + 0];
                sp[9 * 32] = fca[mf][k + 1];
            }
            __syncthreads();
            {
                const int mf = ks >> 1, rp = ks & 1, k = rp * 2;
                float g8[8], f2[2];
                #pragma unroll
                for (int nf = 0; nf < 4; nf++)
                    #pragma unroll
                    for (int cc = 0; cc < 2; cc++)
                        g8[nf * 2 + cc] = acc[mf][nf][k + cc];
                f2[0] = fca[mf][k + 0]; f2[1] = fca[mf][k + 1];
                #pragma unroll
                for (int wi = 0; wi < 3; wi++) {
                    const float* sp = wscr + (((ks * 2 + m2) * 3 + wi) * 10) * 32 + lane;
                    #pragma unroll
                    for (int e = 0; e < 8; e++) g8[e] += sp[e * 32];
                    f2[0] += sp[8 * 32]; f2[1] += sp[9 * 32];
                }
                const int b = m2 * 32 + mf * 16 + rp * 8 + r;
                float* crow = cS + l * 64 * 8;
                #pragma unroll
                for (int ug = 0; ug < 2; ug++) {
                    const int u = ug * 4 + a4;
                    float iv = g8[(ug * 2 + 0) * 2 + 0] + biasS[l * 32 + ug * 16 + a4 * 2 + 0];
                    float fv = g8[(ug * 2 + 0) * 2 + 1] + biasS[l * 32 + ug * 16 + a4 * 2 + 1];
                    float gv = g8[(ug * 2 + 1) * 2 + 0] + biasS[l * 32 + ug * 16 + 8 + a4 * 2 + 0];
                    float ov = g8[(ug * 2 + 1) * 2 + 1] + biasS[l * 32 + ug * 16 + 8 + a4 * 2 + 1];
                    float cn = sig_(fv) * crow[b * 8 + u] + sig_(iv) * tanhf(gv);
                    crow[b * 8 + u] = cn;
                    hdst[b * HID + j0 + u] = __float2half_rn(sig_(ov) * tanhf(cn));
                }
                if (fc_phase) {
                    float* op = out + (size_t)(t - 1) * BATCH * HID;
                    op[b * HID + j0 + a4 * 2 + 0] = f2[0] + fcbS[a4 * 2 + 0];
                    op[b * HID + j0 + a4 * 2 + 1] = f2[1] + fcbS[a4 * 2 + 1];
                }
            }
            gbar_arrive();
            barTarget += NCTA;
            if (!last_phase) {
                // stage next phase's part-A chunk 1 (chunk 0 staged at B kc=6)
                stage_act(xbufS + s_stage * ABUFH, nhsrc, KC, tid);
                cp_commit();
                s_stage = NX3(s_stage);
            }
        }
    }

    // ===== final FC for t = T-1 (x = h1 written at t=127, parity 1) =====
    {
        gbar_wait(barTarget);
        const __half* xsrc = g_hbuf + (2 + 1) * BATCH * HID;
        const __half* wsrc = g_Wst + (size_t)(0 * NCTA + cta) * 40 * HID;
        float fca[2][4] = {{0,0,0,0},{0,0,0,0}};
        #pragma unroll
        for (int i = 0; i < 2; i++) {
            stage_act(xbufS + s_stage * ABUFH, xsrc, i * KC, tid);
            stage_w40(wbufS + w_stage * WBUFH, wsrc, i * KC, tid);
            cp_commit();
            s_stage = NX3(s_stage); w_stage = NX3(w_stage);
        }
        #pragma unroll 1
        for (int kc = 0; kc < NKC; kc++) {
            cp_wait<1>();
            __syncthreads();
            if (kc + 2 < NKC) {
                stage_act(xbufS + s_stage * ABUFH, xsrc, (kc + 2) * KC, tid);
                stage_w40(wbufS + w_stage * WBUFH, wsrc, (kc + 2) * KC, tid);
                s_stage = NX3(s_stage); w_stage = NX3(w_stage);
            }
            cp_commit();
            const unsigned xd = (unsigned)s_cons * ABUF;
            const unsigned wd = (unsigned)w_cons * WBUF;
            s_cons = NX3(s_cons); w_cons = NX3(w_cons);
            #pragma unroll
            for (int j = 0; j < 2; j++) {
                const int k16 = ks + j * 4;
                unsigned f0, f1;
                ldsm_x2(f0, f1, fcB0 + wd + k16 * 32);
                #pragma unroll
                for (int mf = 0; mf < 2; mf++) {
                    unsigned a0, a1, a2, a3;
                    ldsm_x4(a0, a1, a2, a3, xbA0[mf] + xd + k16 * 32);
                    hmma(fca[mf], a0, a1, a2, a3, f0, f1);
                }
            }
        }
        // distributed FC epilogue (same ownership scheme, SoA scratch)
        __syncthreads();
        #pragma unroll
        for (int bi = 0; bi < 4; bi++) {
            if (bi == ks) continue;
            const int wi = (ks < bi) ? ks : ks - 1;
            float* sp = wscr + (((bi * 2 + m2) * 3 + wi) * 10) * 32 + lane;
            const int mf = bi >> 1, k = (bi & 1) * 2;
            sp[8 * 32] = fca[mf][k + 0];
            sp[9 * 32] = fca[mf][k + 1];
        }
        __syncthreads();
        {
            const int mf = ks >> 1, rp = ks & 1, k = rp * 2;
            float f2[2] = { fca[mf][k + 0], fca[mf][k + 1] };
            #pragma unroll
            for (int wi = 0; wi < 3; wi++) {
                const float* sp = wscr + (((ks * 2 + m2) * 3 + wi) * 10) * 32 + lane;
                f2[0] += sp[8 * 32]; f2[1] += sp[9 * 32];
            }
            const int b = m2 * 32 + mf * 16 + rp * 8 + r;
            float* op = out + (size_t)(TSTEPS - 1) * BATCH * HID;
            op[b * HID + j0 + a4 * 2 + 0] = f2[0] + fcbS[a4 * 2 + 0];
            op[b * HID + j0 + a4 * 2 + 1] = f2[1] + fcbS[a4 * 2 + 1];
        }
    }
}

// ---------------- host launch -----------------------------------------------
extern "C" void kernel_launch(void* const* d_in, const int* in_sizes, int n_in,
                              void* d_out, int out_size) {
    const float* h0  = (const float*)d_in[0];
    const float* Wih = (const float*)d_in[1];
    const float* Whh = (const float*)d_in[2];
    const float* bih = (const float*)d_in[3];
    const float* bhh = (const float*)d_in[4];
    const float* Wfc = (const float*)d_in[5];
    const float* bfc = (const float*)d_in[6];
    float* out = (float*)d_out;

    const int smem = (2 * 32 * SR + 3 * 64 * SA + 3 * 40 * SW) * 2
                   + (2 * 64 * 8 + 64 + 8) * 4;
    cudaFuncSetAttribute(lstm_persist, cudaFuncAttributeMaxDynamicSharedMemorySize, smem);

    prep_all<<<2048, 256>>>(Wih, Whh, h0, Wfc);
    lstm_persist<<<NCTA, THREADS, smem>>>(bih, bhh, bfc, out);
}

// round 14
// speedup vs baseline: 1.5928x; 1.5347x over previous
#include <cuda_runtime.h>
#include <cuda_fp16.h>
#include <math.h>

// Persistent-kernel LSTM decoder. B=64, H=1024, L=2, T=128.
// 128 CTAs (1/SM), 256 threads (8 warps). R9-R11 core: warp=(ks,m2) 32x32
// tile over k16s {ks,ks+4}; release-atomic grid barrier; R11 epilogue
// (compile-time register indexing -- R12/R13's runtime-indexed epilogue
// spilled the accumulators to local memory and regressed 50%).
// R14: ACTIVATION IDENTITY -- phase(t,l) part-A h-matrix == previous
// phase's part-B x-matrix. Part B writes x into 8 persistent SMEM slots;
// part A reads them with ZERO act streaming (only streams Whh, 8KB/chunk,
// fully hidden behind compute). Whh is now streamed, not resident.
// t==0: both layers' part A have h==0 -> skipped entirely.

#define BATCH   64
#define HID     1024
#define TSTEPS  128
#define NCTA    128
#define THREADS 256
#define SA      136    // act slot row stride (halfs)
#define SW      136    // streamed weight row stride (halfs)
#define KC      128    // K chunk
#define NKC     8      // chunks per matrix
#define NX3(s)  (((s) + 1 == 3) ? 0 : (s) + 1)

// ---------------- device globals (pre-permuted fp16 weights + state) -------
__device__ __half g_Wst[2 * NCTA * 40 * HID];     // [l][cta][40 rows][k]: 32 Wih + 8 FC
__device__ __half g_Whh_p[2 * NCTA * 32 * HID];   // [l][cta][32][k] recurrent
__device__ __half g_hbuf[4 * BATCH * HID];        // [l*2+parity][b][h]
__device__ __half g_x0[BATCH * HID];
__device__ unsigned g_bar;

// ---------------- small asm helpers ---------------------------------------
__device__ __forceinline__ unsigned sptr(const void* p) {
    return (unsigned)__cvta_generic_to_shared(p);
}
__device__ __forceinline__ void cp16(void* s, const void* g) {      // weights (.ca)
    asm volatile("cp.async.ca.shared.global [%0], [%1], 16;" :: "r"(sptr(s)), "l"(g));
}
__device__ __forceinline__ void cp16cg(void* s, const void* g) {    // acts (.cg)
    asm volatile("cp.async.cg.shared.global [%0], [%1], 16;" :: "r"(sptr(s)), "l"(g));
}
__device__ __forceinline__ void cp_commit() {
    asm volatile("cp.async.commit_group;");
}
template<int N> __device__ __forceinline__ void cp_wait() {
    asm volatile("cp.async.wait_group %0;" :: "n"(N));
}
__device__ __forceinline__ void ldsm_x4(unsigned &r0, unsigned &r1, unsigned &r2, unsigned &r3, unsigned a) {
    asm volatile("ldmatrix.sync.aligned.m8n8.x4.shared.b16 {%0,%1,%2,%3}, [%4];"
                 : "=r"(r0), "=r"(r1), "=r"(r2), "=r"(r3) : "r"(a));
}
__device__ __forceinline__ void ldsm_x2(unsigned &r0, unsigned &r1, unsigned a) {
    asm volatile("ldmatrix.sync.aligned.m8n8.x2.shared.b16 {%0,%1}, [%2];"
                 : "=r"(r0), "=r"(r1) : "r"(a));
}
__device__ __forceinline__ void hmma(float d[4], unsigned a0, unsigned a1, unsigned a2, unsigned a3,
                                     unsigned b0, unsigned b1) {
    asm volatile("mma.sync.aligned.m16n8k16.row.col.f32.f16.f16.f32 "
                 "{%0,%1,%2,%3},{%4,%5,%6,%7},{%8,%9},{%0,%1,%2,%3};"
                 : "+f"(d[0]), "+f"(d[1]), "+f"(d[2]), "+f"(d[3])
                 : "r"(a0), "r"(a1), "r"(a2), "r"(a3), "r"(b0), "r"(b1));
}
__device__ __forceinline__ float sig_(float x) { return 1.0f / (1.0f + __expf(-x)); }

// ---------------- single merged prep kernel ---------------------------------
// permuted col index pn -> (gate, unit):
//   nn=pn&15; half=nn>>3; a=(nn&7)>>1; s=nn&1; gate=half*2+s; unit=(pn>>4)*4+a
__global__ void prep_all(const float* __restrict__ Wih, const float* __restrict__ Whh,
                         const float* __restrict__ h0,  const float* __restrict__ Wfc) {
    int i = blockIdx.x * blockDim.x + threadIdx.x;
    int stride = gridDim.x * blockDim.x;
    const int totalG = 2 * NCTA * 32 * HID;
    for (int e = i; e < totalG; e += stride) {
        int k = e & (HID - 1);
        int pn = (e >> 10) & 31;
        int cta = (e >> 15) & (NCTA - 1);
        int l = e >> 22;
        int nn = pn & 15, half = nn >> 3, a = (nn & 7) >> 1, s = nn & 1;
        int gate = half * 2 + s, unit = (pn >> 4) * 4 + a;
        size_t src = (size_t)l * 4 * HID * HID + (size_t)(gate * HID + cta * 8 + unit) * HID + k;
        g_Whh_p[e] = __float2half_rn(Whh[src]);
        g_Wst[(size_t)((l * NCTA + cta) * 40 + pn) * HID + k] = __float2half_rn(Wih[src]);
    }
    const int totalF = 2 * NCTA * 8 * HID;
    for (int e = i; e < totalF; e += stride) {
        int k = e & (HID - 1);
        int u = (e >> 10) & 7;
        int cta = (e >> 13) & (NCTA - 1);
        int l = e >> 20;
        g_Wst[(size_t)((l * NCTA + cta) * 40 + 32 + u) * HID + k] =
            __float2half_rn(Wfc[(size_t)(cta * 8 + u) * HID + k]);
    }
    for (int e = i; e < BATCH * HID; e += stride) g_x0[e] = __float2half_rn(h0[e]);
    for (int e = i; e < 4 * BATCH * HID; e += stride) g_hbuf[e] = __float2half_rn(0.0f);
    if (i == 0) g_bar = 0;
}

// ---------------- split grid barrier ---------------------------------------
__device__ __forceinline__ void gbar_arrive() {
    __syncthreads();
    if (threadIdx.x == 0)
        asm volatile("red.release.gpu.add.u32 [%0], %1;" :: "l"(&g_bar), "r"(1u) : "memory");
}
__device__ __forceinline__ void gbar_wait(unsigned target) {
    if (threadIdx.x == 0) {
        unsigned v;
        do {
            asm volatile("ld.acquire.gpu.u32 %0, [%1];" : "=r"(v) : "l"(&g_bar));
        } while (v < target);
    }
    __syncthreads();
}

// ---------------- staging ---------------------------------------------------
__device__ __forceinline__ void stage_act(__half* dst, const __half* src, int k0, int tid) {
    #pragma unroll
    for (int i = 0; i < 4; i++) {
        int e = tid + i * THREADS;          // 1024 ops: 64 rows x 16 segs
        int r = e >> 4, sg = e & 15;
        cp16cg(dst + r * SA + sg * 8, src + r * HID + k0 + sg * 8);
    }
}
__device__ __forceinline__ void stage_w40(__half* dst, const __half* src, int k0, int tid) {
    #pragma unroll
    for (int i = 0; i < 3; i++) {
        int e = tid + i * THREADS;          // 640 ops: 40 rows x 16 segs
        if (e < 640) {
            int r = e >> 4, sg = e & 15;
            cp16(dst + r * SW + sg * 8, src + r * HID + k0 + sg * 8);
        }
    }
}
__device__ __forceinline__ void stage_w32(__half* dst, const __half* src, int k0, int tid) {
    #pragma unroll
    for (int i = 0; i < 2; i++) {
        int e = tid + i * THREADS;          // 512 ops: 32 rows x 16 segs
        int r = e >> 4, sg = e & 15;
        cp16(dst + r * SW + sg * 8, src + r * HID + k0 + sg * 8);
    }
}

// ---------------- main persistent kernel ------------------------------------
__global__ __launch_bounds__(THREADS, 1) void lstm_persist(
    const float* __restrict__ bih, const float* __restrict__ bhh,
    const float* __restrict__ bfc, float* __restrict__ out)
{
    extern __shared__ __align__(16) unsigned char smem_raw[];
    __half* actS  = (__half*)smem_raw;            // [8 slots][64][SA] persistent acts
    __half* wringS = actS + 8 * 64 * SA;          // [3][40][SW] weight ring (+ epi scratch)
    float*  cS    = (float*)(wringS + 3 * 40 * SW);// [2][64][8]
    float*  biasS = cS + 2 * 64 * 8;              // [2][32]
    float*  fcbS  = biasS + 64;                   // [8]
    float*  wscr  = (float*)wringS;               // epilogue reduce scratch

    const int tid  = threadIdx.x;
    const int warp = tid >> 5;
    const int lane = tid & 31;
    const int m2   = warp & 1;     // 32-row M half
    const int ks   = warp >> 1;    // k16 split (k16 in {ks, ks+4})
    const int cta  = blockIdx.x;
    const int j0   = cta * 8;

    const unsigned ABUF = 64 * SA * 2;   // act slot stride (bytes)
    const unsigned WBUF = 40 * SW * 2;   // W slot stride (bytes)
    const int ABUFH = 64 * SA;           // act slot stride (halfs)
    const int WBUFH = 40 * SW;

    // ---- biases / cell state ----
    if (tid < 64) {
        int l = tid >> 5, pn = tid & 31;
        int nn = pn & 15, half = nn >> 3, a = (nn & 7) >> 1, s = nn & 1;
        int gate = half * 2 + s, unit = (pn >> 4) * 4 + a;
        int row = gate * HID + j0 + unit;
        biasS[l * 32 + pn] = bih[l * 4 * HID + row] + bhh[l * 4 * HID + row];
    }
    if (tid < 8) fcbS[tid] = bfc[j0 + tid];
    #pragma unroll
    for (int i = 0; i < 4; i++) cS[tid + i * THREADS] = 0.0f;
    __syncthreads();

    // per-lane fragment base addresses (slot delta added at use)
    const unsigned xbA0[2] = {
        sptr(actS) + ((m2 * 32 + 0  + (lane & 15)) * SA + (lane >> 4) * 8) * 2,
        sptr(actS) + ((m2 * 32 + 16 + (lane & 15)) * SA + (lane >> 4) * 8) * 2 };
    const unsigned wbB0[2] = {
        sptr(wringS) + ((0  + (lane & 15)) * SW + (lane >> 4) * 8) * 2,
        sptr(wringS) + ((16 + (lane & 15)) * SW + (lane >> 4) * 8) * 2 };
    const unsigned fcB0 =
        sptr(wringS) + ((32 + (lane & 7)) * SW + ((lane >> 3) & 1) * 8) * 2;

    unsigned barTarget = 0;
    const int r = lane >> 2, a4 = lane & 3;

    // W ring slot state (continuous across phases)
    int w_stage = 0, w_cons = 0;

    for (int t = 0; t < TSTEPS; t++) {
        const int p = t & 1, q = p ^ 1;
        #pragma unroll 1
        for (int l = 0; l < 2; l++) {
            const __half* xsrc = (l == 0)
                ? ((t == 0) ? g_x0 : g_hbuf + (2 + q) * BATCH * HID)
                : g_hbuf + (0 + p) * BATCH * HID;
            __half* hdst = g_hbuf + (l * 2 + p) * BATCH * HID;
            const __half* wsrc  = g_Wst   + (size_t)(l * NCTA + cta) * 40 * HID;
            const __half* whsrc = g_Whh_p + (size_t)(l * NCTA + cta) * 32 * HID;
            const bool fc_phase = (l == 0) && (t > 0);

            float acc[2][4][4];
            #pragma unroll
            for (int a = 0; a < 2; a++)
                #pragma unroll
                for (int b = 0; b < 4; b++)
                    #pragma unroll
                    for (int c2 = 0; c2 < 4; c2++) acc[a][b][c2] = 0.0f;
            float fca[2][4] = {{0,0,0,0},{0,0,0,0}};

            // ===== part A: h_rec @ Whh. h is ALREADY in the 8 act slots
            //       (written as x by the previous phase's part B).
            //       t==0: h == 0 for both layers -> part A skipped. =====
            if (t > 0) {
                stage_w32(wringS + w_stage * WBUFH, whsrc, 0, tid); cp_commit();
                w_stage = NX3(w_stage);
                stage_w32(wringS + w_stage * WBUFH, whsrc, KC, tid); cp_commit();
                w_stage = NX3(w_stage);
                #pragma unroll 1
                for (int kc = 0; kc < NKC; kc++) {
                    cp_wait<1>();
                    __syncthreads();
                    if (kc + 2 < NKC) {
                        stage_w32(wringS + w_stage * WBUFH, whsrc, (kc + 2) * KC, tid);
                        w_stage = NX3(w_stage);
                    }
                    cp_commit();
                    const unsigned xd = (unsigned)kc * ABUF;
                    const unsigned wd = (unsigned)w_cons * WBUF;
                    w_cons = NX3(w_cons);
                    #pragma unroll
                    for (int j = 0; j < 2; j++) {
                        const int k16 = ks + j * 4;
                        unsigned a0[2][4], b0[2][4];
                        #pragma unroll
                        for (int mf = 0; mf < 2; mf++)
                            ldsm_x4(a0[mf][0], a0[mf][1], a0[mf][2], a0[mf][3],
                                    xbA0[mf] + xd + k16 * 32);
                        #pragma unroll
                        for (int cg = 0; cg < 2; cg++)
                            ldsm_x4(b0[cg][0], b0[cg][1], b0[cg][2], b0[cg][3],
                                    wbB0[cg] + wd + k16 * 32);
                        #pragma unroll
                        for (int mf = 0; mf < 2; mf++)
                            #pragma unroll
                            for (int cg = 0; cg < 2; cg++) {
                                hmma(acc[mf][cg * 2 + 0], a0[mf][0], a0[mf][1], a0[mf][2], a0[mf][3],
                                     b0[cg][0], b0[cg][2]);
                                hmma(acc[mf][cg * 2 + 1], a0[mf][0], a0[mf][1], a0[mf][2], a0[mf][3],
                                     b0[cg][1], b0[cg][3]);
                            }
                    }
                }
            }

            // ===== barrier wait (mostly satisfied already) =====
            gbar_wait(barTarget);

            // ===== part B: x @ [Wih | Wfc]; x lands in slots 0..7 and
            //       becomes next phase's part-A h. =====
            #pragma unroll
            for (int i = 0; i < 2; i++) {
                stage_act(actS + i * ABUFH, xsrc, i * KC, tid);
                stage_w40(wringS + w_stage * WBUFH, wsrc, i * KC, tid);
                cp_commit();
                w_stage = NX3(w_stage);
            }
            #pragma unroll 1
            for (int kc = 0; kc < NKC; kc++) {
                cp_wait<1>();
                __syncthreads();
                if (kc + 2 < NKC) {
                    stage_act(actS + (kc + 2) * ABUFH, xsrc, (kc + 2) * KC, tid);
                    stage_w40(wringS + w_stage * WBUFH, wsrc, (kc + 2) * KC, tid);
                    w_stage = NX3(w_stage);
                }
                cp_commit();
                const unsigned xd = (unsigned)kc * ABUF;
                const unsigned wd = (unsigned)w_cons * WBUF;
                w_cons = NX3(w_cons);
                #pragma unroll
                for (int j = 0; j < 2; j++) {
                    const int k16 = ks + j * 4;
                    unsigned a0[2][4], b0[2][4];
                    #pragma unroll
                    for (int mf = 0; mf < 2; mf++)
                        ldsm_x4(a0[mf][0], a0[mf][1], a0[mf][2], a0[mf][3],
                                xbA0[mf] + xd + k16 * 32);
                    #pragma unroll
                    for (int cg = 0; cg < 2; cg++)
                        ldsm_x4(b0[cg][0], b0[cg][1], b0[cg][2], b0[cg][3],
                                wbB0[cg] + wd + k16 * 32);
                    #pragma unroll
                    for (int mf = 0; mf < 2; mf++)
                        #pragma unroll
                        for (int cg = 0; cg < 2; cg++) {
                            hmma(acc[mf][cg * 2 + 0], a0[mf][0], a0[mf][1], a0[mf][2], a0[mf][3],
                                 b0[cg][0], b0[cg][2]);
                            hmma(acc[mf][cg * 2 + 1], a0[mf][0], a0[mf][1], a0[mf][2], a0[mf][3],
                                 b0[cg][1], b0[cg][3]);
                        }
                    if (fc_phase) {
                        unsigned f0, f1;
                        ldsm_x2(f0, f1, fcB0 + wd + k16 * 32);
                        #pragma unroll
                        for (int mf = 0; mf < 2; mf++)
                            hmma(fca[mf], a0[mf][0], a0[mf][1], a0[mf][2], a0[mf][3], f0, f1);
                    }
                }
            }

            // ===== epilogue (R11 form: compile-time register indexing) ======
            __syncthreads();           // all W-ring reads done before scratch reuse
            if (ks > 0) {
                float* sp = wscr + (((ks - 1) * 2 + m2) * 32 + lane) * 40;
                #pragma unroll
                for (int mf = 0; mf < 2; mf++)
                    #pragma unroll
                    for (int nf = 0; nf < 4; nf++)
                        #pragma unroll
                        for (int c2 = 0; c2 < 4; c2++)
                            sp[(mf * 4 + nf) * 4 + c2] = acc[mf][nf][c2];
                #pragma unroll
                for (int mf = 0; mf < 2; mf++)
                    #pragma unroll
                    for (int c2 = 0; c2 < 4; c2++)
                        sp[32 + mf * 4 + c2] = fca[mf][c2];
            }
            __syncthreads();
            if (ks == 0) {
                #pragma unroll
                for (int sl = 0; sl < 3; sl++) {
                    const float* sp = wscr + ((sl * 2 + m2) * 32 + lane) * 40;
                    #pragma unroll
                    for (int mf = 0; mf < 2; mf++)
                        #pragma unroll
                        for (int nf = 0; nf < 4; nf++)
                            #pragma unroll
                            for (int c2 = 0; c2 < 4; c2++)
                                acc[mf][nf][c2] += sp[(mf * 4 + nf) * 4 + c2];
                    #pragma unroll
                    for (int mf = 0; mf < 2; mf++)
                        #pragma unroll
                        for (int c2 = 0; c2 < 4; c2++)
                            fca[mf][c2] += sp[32 + mf * 4 + c2];
                }

                float* crow = cS + l * 64 * 8;
                float* op = out + (size_t)(t - 1) * BATCH * HID;
                #pragma unroll
                for (int mf = 0; mf < 2; mf++) {
                    #pragma unroll
                    for (int rp = 0; rp < 2; rp++) {
                        const int b = m2 * 32 + mf * 16 + rp * 8 + r;
                        const int k = rp * 2;
                        #pragma unroll
                        for (int ug = 0; ug < 2; ug++) {
                            const int u = ug * 4 + a4;
                            float iv = acc[mf][ug * 2 + 0][k + 0] + biasS[l * 32 + ug * 16 + a4 * 2 + 0];
                            float fv = acc[mf][ug * 2 + 0][k + 1] + biasS[l * 32 + ug * 16 + a4 * 2 + 1];
                            float gv = acc[mf][ug * 2 + 1][k + 0] + biasS[l * 32 + ug * 16 + 8 + a4 * 2 + 0];
                            float ov = acc[mf][ug * 2 + 1][k + 1] + biasS[l * 32 + ug * 16 + 8 + a4 * 2 + 1];
                            float cn = sig_(fv) * crow[b * 8 + u] + sig_(iv) * tanhf(gv);
                            crow[b * 8 + u] = cn;
                            hdst[b * HID + j0 + u] = __float2half_rn(sig_(ov) * tanhf(cn));
                        }
                        if (fc_phase) {
                            op[b * HID + j0 + a4 * 2 + 0] = fca[mf][k + 0] + fcbS[a4 * 2 + 0];
                            op[b * HID + j0 + a4 * 2 + 1] = fca[mf][k + 1] + fcbS[a4 * 2 + 1];
                        }
                    }
                }
            }
            gbar_arrive();
            barTarget += NCTA;
        }
    }

    // ===== final FC for t = T-1 (x = h1 written at t=127, parity 1) =====
    {
        gbar_wait(barTarget);
        const __half* xsrc = g_hbuf + (2 + 1) * BATCH * HID;
        const __half* wsrc = g_Wst + (size_t)(0 * NCTA + cta) * 40 * HID;
        float fca[2][4] = {{0,0,0,0},{0,0,0,0}};
        #pragma unroll
        for (int i = 0; i < 2; i++) {
            stage_act(actS + i * ABUFH, xsrc, i * KC, tid);
            stage_w40(wringS + w_stage * WBUFH, wsrc, i * KC, tid);
            cp_commit();
            w_stage = NX3(w_stage);
        }
        #pragma unroll 1
        for (int kc = 0; kc < NKC; kc++) {
            cp_wait<1>();
            __syncthreads();
            if (kc + 2 < NKC) {
                stage_act(actS + (kc + 2) * ABUFH, xsrc, (kc + 2) * KC, tid);
                stage_w40(wringS + w_stage * WBUFH, wsrc, (kc + 2) * KC, tid);
                w_stage = NX3(w_stage);
            }
            cp_commit();
            const unsigned xd = (unsigned)kc * ABUF;
            const unsigned wd = (unsigned)w_cons * WBUF;
            w_cons = NX3(w_cons);
            #pragma unroll
            for (int j = 0; j < 2; j++) {
                const int k16 = ks + j * 4;
                unsigned f0, f1;
                ldsm_x2(f0, f1, fcB0 + wd + k16 * 32);
                #pragma unroll
                for (int mf = 0; mf < 2; mf++) {
                    unsigned a0, a1, a2, a3;
                    ldsm_x4(a0, a1, a2, a3, xbA0[mf] + xd + k16 * 32);
                    hmma(fca[mf], a0, a1, a2, a3, f0, f1);
                }
            }
        }
        __syncthreads();
        if (ks > 0) {
            float* sp = wscr + (((ks - 1) * 2 + m2) * 32 + lane) * 40;
            #pragma unroll
            for (int mf = 0; mf < 2; mf++)
                #pragma unroll
                for (int c2 = 0; c2 < 4; c2++)
                    sp[32 + mf * 4 + c2] = fca[mf][c2];
        }
        __syncthreads();
        if (ks == 0) {
            #pragma unroll
            for (int sl = 0; sl < 3; sl++) {
                const float* sp = wscr + ((sl * 2 + m2) * 32 + lane) * 40;
                #pragma unroll
                for (int mf = 0; mf < 2; mf++)
                    #pragma unroll
                    for (int c2 = 0; c2 < 4; c2++)
                        fca[mf][c2] += sp[32 + mf * 4 + c2];
            }
            float* op = out + (size_t)(TSTEPS - 1) * BATCH * HID;
            #pragma unroll
            for (int mf = 0; mf < 2; mf++)
                #pragma unroll
                for (int rp = 0; rp < 2; rp++) {
                    const int b = m2 * 32 + mf * 16 + rp * 8 + r;
                    const int k = rp * 2;
                    op[b * HID + j0 + a4 * 2 + 0] = fca[mf][k + 0] + fcbS[a4 * 2 + 0];
                    op[b * HID + j0 + a4 * 2 + 1] = fca[mf][k + 1] + fcbS[a4 * 2 + 1];
                }
        }
    }
}

// ---------------- host launch -----------------------------------------------
extern "C" void kernel_launch(void* const* d_in, const int* in_sizes, int n_in,
                              void* d_out, int out_size) {
    const float* h0  = (const float*)d_in[0];
    const float* Wih = (const float*)d_in[1];
    const float* Whh = (const float*)d_in[2];
    const float* bih = (const float*)d_in[3];
    const float* bhh = (const float*)d_in[4];
    const float* Wfc = (const float*)d_in[5];
    const float* bfc = (const float*)d_in[6];
    float* out = (float*)d_out;

    const int smem = (8 * 64 * SA + 3 * 40 * SW) * 2
                   + (2 * 64 * 8 + 64 + 8) * 4;
    cudaFuncSetAttribute(lstm_persist, cudaFuncAttributeMaxDynamicSharedMemorySize, smem);

    prep_all<<<2048, 256>>>(Wih, Whh, h0, Wfc);
    lstm_persist<<<NCTA, THREADS, smem>>>(bih, bhh, bfc, out);
}